// round 17
// baseline (speedup 1.0000x reference)
#include <cuda_runtime.h>
#include <cuda_fp16.h>
#include <stdint.h>

#define N_NODES 1000000
#define F 16
#define MAX_E 4000000
#define CAP 16                 // bucket slots per node (64B)
#define OVMAX 2048

// Scratch (allocation-free rule: __device__ globals)
__device__ __half g_h[(size_t)N_NODES * F];       // x@W unscaled, fp16 (32MB)
__device__ float  g_dinv[N_NODES];                // rsqrt(deg + 1)
__device__ int    g_cnt[N_NODES + 1];             // cursors->degree; [n]=ovf ctr
__device__ int    g_src[(size_t)N_NODES * CAP];   // bucketed src ids (64MB)
__device__ int2   g_over[OVMAX];                  // overflow edges (c, r)

// ---------------------------------------------------------------------------
// K1: single-pass bucket scatter. slot = atomicAdd(cursor[c]); final counter
// value = degree. Rare slot>=CAP goes to overflow list (counter at g_cnt[n]).
// ---------------------------------------------------------------------------
__global__ void k_scatter(const int4* __restrict__ row4,
                          const int4* __restrict__ col4,
                          int E4, int E, int n) {
    int t = blockIdx.x * blockDim.x + threadIdx.x;
    if (t < E4) {
        int4 r4 = __ldg(&row4[t]);
        int4 c4 = __ldg(&col4[t]);
#pragma unroll
        for (int q = 0; q < 4; q++) {
            int r = (&r4.x)[q];
            int c = (&c4.x)[q];
            if ((unsigned)c < (unsigned)n && (unsigned)r < (unsigned)n) {
                int slot = atomicAdd(&g_cnt[c], 1);
                if (slot < CAP) {
                    g_src[(size_t)c * CAP + slot] = r;
                } else {
                    int o = atomicAdd(&g_cnt[n], 1);
                    if (o < OVMAX) g_over[o] = make_int2(c, r);
                }
            }
        }
    }
    int tail = E & 3;
    if (t < tail) {
        const int* row = (const int*)row4;
        const int* col = (const int*)col4;
        int e = E - 1 - t;
        int r = row[e], c = col[e];
        if ((unsigned)c < (unsigned)n && (unsigned)r < (unsigned)n) {
            int slot = atomicAdd(&g_cnt[c], 1);
            if (slot < CAP) {
                g_src[(size_t)c * CAP + slot] = r;
            } else {
                int o = atomicAdd(&g_cnt[n], 1);
                if (o < OVMAX) g_over[o] = make_int2(c, r);
            }
        }
    }
}

// ---------------------------------------------------------------------------
// K2: h = x @ W -> fp16 (UNSCALED -- no dependency on scatter/degrees).
// Runs on a forked stream concurrently with k_scatter.
// ---------------------------------------------------------------------------
__global__ void __launch_bounds__(256)
k_h(const float4* __restrict__ x4, const float* __restrict__ W, int n) {
    __shared__ float sW[F * F];
    sW[threadIdx.x] = W[threadIdx.x];     // blockDim == 256 == F*F
    __syncthreads();

    int i = blockIdx.x * 256 + threadIdx.x;
    if (i >= n) return;

    float4 xv0 = x4[(size_t)i * 4 + 0];
    float4 xv1 = x4[(size_t)i * 4 + 1];
    float4 xv2 = x4[(size_t)i * 4 + 2];
    float4 xv3 = x4[(size_t)i * 4 + 3];
    float xr[F] = {xv0.x, xv0.y, xv0.z, xv0.w,
                   xv1.x, xv1.y, xv1.z, xv1.w,
                   xv2.x, xv2.y, xv2.z, xv2.w,
                   xv3.x, xv3.y, xv3.z, xv3.w};

    float acc[F];
#pragma unroll
    for (int j = 0; j < F; j++) acc[j] = 0.0f;
#pragma unroll
    for (int k = 0; k < F; k++) {
        float xk = xr[k];
#pragma unroll
        for (int j = 0; j < F; j++) acc[j] = fmaf(xk, sW[k * F + j], acc[j]);
    }

    uint4 hpk[2];
    __half2* hh = reinterpret_cast<__half2*>(&hpk[0]);
#pragma unroll
    for (int q = 0; q < 8; q++)
        hh[q] = __floats2half2_rn(acc[2 * q], acc[2 * q + 1]);
    uint4* hp = reinterpret_cast<uint4*>(g_h + (size_t)i * F);
    hp[0] = hpk[0];
    hp[1] = hpk[1];
}

// ---------------------------------------------------------------------------
// K2b: dinv = rsqrt(deg + 1). Tiny streaming kernel (after scatter).
// ---------------------------------------------------------------------------
__global__ void __launch_bounds__(256)
k_dinv(int n) {
    int i = blockIdx.x * 256 + threadIdx.x;
    if (i < n) g_dinv[i] = rsqrtf((float)g_cnt[i] + 1.0f);
}

// ---------------------------------------------------------------------------
// K3: per-dst gather, 4 threads per node (feature split, 8B quarters).
// MLP-maximized unrolled slots; per-slot dinv[s] gather (L2-hot 4MB) FMA'd.
// out = di * (sum_s dinv_s * h_s) + di^2 * h_i + b.
// ---------------------------------------------------------------------------
__global__ void __launch_bounds__(256)
k_out(const float* __restrict__ b, float4* __restrict__ out4, int n) {
    int tid  = threadIdx.x;
    int lane = tid & 3;
    int i    = blockIdx.x * 64 + (tid >> 2);
    if (i >= n) return;

    float4 bq = reinterpret_cast<const float4*>(b)[lane];

    int cnt = __ldg(&g_cnt[i]);
    float di = g_dinv[i];
    int m = cnt < CAP ? cnt : CAP;

    const int4* bkt = reinterpret_cast<const int4*>(g_src + (size_t)i * CAP);
    int4 b0 = __ldg(&bkt[0]);
    int4 b1 = __ldg(&bkt[1]);
    int sid[8] = {b0.x, b0.y, b0.z, b0.w, b1.x, b1.y, b1.z, b1.w};

    const uint2 z2 = make_uint2(0u, 0u);
    uint2 p[8];
    float ds[8];
#pragma unroll
    for (int k = 0; k < 8; k++) {
        bool v = (k < m);
        ds[k] = v ? __ldg(&g_dinv[sid[k]]) : 0.0f;
        p[k]  = v ? __ldg(&reinterpret_cast<const uint2*>(
                              g_h + (size_t)sid[k] * F)[lane])
                  : z2;
    }

    float4 acc = make_float4(0.f, 0.f, 0.f, 0.f);
#pragma unroll
    for (int k = 0; k < 8; k++) {
        float2 f0 = __half22float2(*reinterpret_cast<const __half2*>(&p[k].x));
        float2 f1 = __half22float2(*reinterpret_cast<const __half2*>(&p[k].y));
        acc.x = fmaf(f0.x, ds[k], acc.x);
        acc.y = fmaf(f0.y, ds[k], acc.y);
        acc.z = fmaf(f1.x, ds[k], acc.z);
        acc.w = fmaf(f1.y, ds[k], acc.w);
    }

    if (m > 8) {                           // ~2% of nodes
        int4 b2 = __ldg(&bkt[2]);
        int4 b3 = __ldg(&bkt[3]);
        int sid2[8] = {b2.x, b2.y, b2.z, b2.w, b3.x, b3.y, b3.z, b3.w};
        uint2 q[8];
        float ds2[8];
#pragma unroll
        for (int k = 0; k < 8; k++) {
            bool v = (k + 8 < m);
            ds2[k] = v ? __ldg(&g_dinv[sid2[k]]) : 0.0f;
            q[k]   = v ? __ldg(&reinterpret_cast<const uint2*>(
                                   g_h + (size_t)sid2[k] * F)[lane])
                       : z2;
        }
#pragma unroll
        for (int k = 0; k < 8; k++) {
            float2 f0 = __half22float2(*reinterpret_cast<const __half2*>(&q[k].x));
            float2 f1 = __half22float2(*reinterpret_cast<const __half2*>(&q[k].y));
            acc.x = fmaf(f0.x, ds2[k], acc.x);
            acc.y = fmaf(f0.y, ds2[k], acc.y);
            acc.z = fmaf(f1.x, ds2[k], acc.z);
            acc.w = fmaf(f1.y, ds2[k], acc.w);
        }
    }

    // self-loop: di^2 * h_i;  out = di*acc + di^2*h_i + b
    uint2 pi = reinterpret_cast<const uint2*>(g_h + (size_t)i * F)[lane];
    float2 v0 = __half22float2(*reinterpret_cast<const __half2*>(&pi.x));
    float2 v1 = __half22float2(*reinterpret_cast<const __half2*>(&pi.y));
    float dii = di * di;

    out4[(size_t)i * 4 + lane] = make_float4(
        fmaf(acc.x, di, fmaf(v0.x, dii, bq.x)),
        fmaf(acc.y, di, fmaf(v0.y, dii, bq.y)),
        fmaf(acc.z, di, fmaf(v1.x, dii, bq.z)),
        fmaf(acc.w, di, fmaf(v1.y, dii, bq.w)));
}

// ---------------------------------------------------------------------------
// K4: overflow fixup -- edges whose dst degree > CAP (expected ~0-3 total).
// Adds di_c * dinv_r * h_r into out via vector float REDs.
// ---------------------------------------------------------------------------
__global__ void k_over(float* __restrict__ out, int n) {
    int t = blockIdx.x * blockDim.x + threadIdx.x;
    int m = g_cnt[n];
    if (m > OVMAX) m = OVMAX;
    if (t >= m) return;

    int2 e = g_over[t];
    int c = e.x, r = e.y;
    float s = g_dinv[c] * g_dinv[r];

    const uint4* hp = reinterpret_cast<const uint4*>(g_h + (size_t)r * F);
    uint4 p0 = __ldg(&hp[0]);
    uint4 p1 = __ldg(&hp[1]);
    const __half2* h0 = reinterpret_cast<const __half2*>(&p0);
    const __half2* h1 = reinterpret_cast<const __half2*>(&p1);

    float v[F];
#pragma unroll
    for (int q = 0; q < 4; q++) {
        float2 f = __half22float2(h0[q]);
        v[2 * q] = f.x * s; v[2 * q + 1] = f.y * s;
        float2 g = __half22float2(h1[q]);
        v[8 + 2 * q] = g.x * s; v[8 + 2 * q + 1] = g.y * s;
    }

    float* op = out + (size_t)c * F;
#pragma unroll
    for (int q = 0; q < 4; q++) {
        asm volatile(
            "red.global.add.v4.f32 [%0], {%1, %2, %3, %4};"
            :: "l"(op + q * 4),
               "f"(v[q * 4 + 0]), "f"(v[q * 4 + 1]),
               "f"(v[q * 4 + 2]), "f"(v[q * 4 + 3])
            : "memory");
    }
}

// ---------------------------------------------------------------------------
// launch: fork k_h onto a side stream so it overlaps memset+scatter.
// ---------------------------------------------------------------------------
extern "C" void kernel_launch(void* const* d_in, const int* in_sizes, int n_in,
                              void* d_out, int out_size) {
    const float* x   = (const float*)d_in[0];
    const int*   ei  = (const int*)d_in[1];  // int32 (JAX x64 disabled)
    const float* W   = (const float*)d_in[2];
    const float* b   = (const float*)d_in[3];
    float*       out = (float*)d_out;

    int n = in_sizes[0] / F;   // 1,000,000
    int E = in_sizes[1] / 2;   // 4,000,000
    if (E > MAX_E) E = MAX_E;

    const int T = 256;
    int E4 = E / 4;

    // side stream + events (host-side handles; no device memory)
    cudaStream_t s2;
    cudaStreamCreateWithFlags(&s2, cudaStreamNonBlocking);
    cudaEvent_t evFork, evJoin;
    cudaEventCreateWithFlags(&evFork, cudaEventDisableTiming);
    cudaEventCreateWithFlags(&evJoin, cudaEventDisableTiming);

    // fork: k_h on s2, concurrent with memset+scatter on the main stream
    cudaEventRecord(evFork, 0);
    cudaStreamWaitEvent(s2, evFork, 0);
    k_h<<<(n + T - 1) / T, T, 0, s2>>>((const float4*)x, W, n);
    cudaEventRecord(evJoin, s2);

    // main stream: zero cursors, scatter, dinv
    void* p = nullptr;
    cudaGetSymbolAddress(&p, g_cnt);
    cudaMemsetAsync(p, 0, ((size_t)n + 1) * sizeof(int));
    k_scatter<<<(E4 + T - 1) / T, T>>>((const int4*)ei,
                                       (const int4*)(ei + (size_t)E), E4, E, n);
    k_dinv<<<(n + T - 1) / T, T>>>(n);

    // join, then consume both h and CSR buckets
    cudaStreamWaitEvent(0, evJoin, 0);
    k_out<<<(n * 4 + T - 1) / T, T>>>(b, (float4*)out, n);
    k_over<<<OVMAX / T, T>>>(out, n);
}